// round 11
// baseline (speedup 1.0000x reference)
#include <cuda_runtime.h>
#include <math.h>
#include <stdint.h>

typedef unsigned long long u64;

#define BATCH 8
#define NBOX  300
#define TOPK  20
#define HW    512
#define CROPS 64
#define OC    256
#define FCO   4096

// d_out layout (floats): Objects[8,20,4] | Object_features[8,20,4096] | valid[8,20] | fullframe[8,4096]
#define OBJ_OFF   0
#define FEAT_OFF  640
#define VALID_OFF 656000
#define FULL_OFF  656160

#define KSTEPS 19                      // 147 -> 152 (19 k-steps of 8)
#define NFRAG  (KSTEPS*8*32*4)         // 19456 floats per ct
#define BSMEM_BYTES (KSTEPS*4*32*16)   // 38912 B fragment-packed im2col (64 px)
#define DEC_OFF  BSMEM_BYTES           // int4[152] decode table
#define CONV_SMEM (BSMEM_BYTES + 152*16)   // 41344 B
#define FULL_BLOCKS 4096               // 2 ct * 2 px-half * 128 rows * 8 batch
#define CROP_BLOCKS (BATCH*TOPK*4)     // job * 2 halves * 2 ct

__constant__ float c_mean[3] = {0.485f, 0.456f, 0.406f};
__constant__ float c_istd[3] = {1.0f/0.229f, 1.0f/0.224f, 1.0f/0.225f};

__device__ float g_pooled_full[BATCH*OC];
__device__ float g_pooled_crop[BATCH*TOPK*OC];
__device__ float g_crops[BATCH*TOPK*3*CROPS*CROPS];
__device__ __align__(16) float g_Wt[147*OC];         // [k][oc] for scalar crop conv
__device__ __align__(16) float g_WfragHi[2*NFRAG];   // tf32-hi weight fragments
__device__ __align__(16) float g_WfragLo[2*NFRAG];   // tf32-lo weight fragments
__device__ float g_job_box[BATCH*TOPK*4];
__device__ int   g_job_b[BATCH*TOPK];
__device__ int   g_job_bk[BATCH*TOPK];
__device__ int   g_njobs;
__device__ int   g_lab64;

// ---------------------------------------------------------------- helpers
__device__ __forceinline__ void ffma2(u64 &d, u64 a, u64 b) {
    asm("fma.rn.f32x2 %0, %1, %2, %0;" : "+l"(d) : "l"(a), "l"(b));
}
__device__ __forceinline__ u64 dup2(float a) {
    u64 r; asm("mov.b64 %0, {%1, %1};" : "=l"(r) : "f"(a)); return r;
}
__device__ __forceinline__ void unpack2(u64 v, float &lo, float &hi) {
    asm("mov.b64 {%0, %1}, %2;" : "=f"(lo), "=f"(hi) : "l"(v));
}
__device__ __forceinline__ float tf32r(float a) {
    uint32_t u; asm("cvt.rna.tf32.f32 %0, %1;" : "=r"(u) : "f"(a));
    return __uint_as_float(u);
}
__device__ __forceinline__ void mma_tf32(float* d, const uint32_t* a, uint32_t b0, uint32_t b1) {
    asm volatile(
        "mma.sync.aligned.m16n8k8.row.col.f32.tf32.tf32.f32 "
        "{%0,%1,%2,%3}, {%4,%5,%6,%7}, {%8,%9}, {%0,%1,%2,%3};"
        : "+f"(d[0]), "+f"(d[1]), "+f"(d[2]), "+f"(d[3])
        : "r"(a[0]), "r"(a[1]), "r"(a[2]), "r"(a[3]), "r"(b0), "r"(b1));
}

// ---------------------------------------------------------------- prep
__global__ void prep_kernel(const float* __restrict__ Wc,
                            const long long* __restrict__ lab) {
    int gid = blockIdx.x*256 + threadIdx.x;
    if (gid < BATCH*OC)      g_pooled_full[gid] = 0.f;
    if (gid < BATCH*TOPK*OC) g_pooled_crop[gid] = 0.f;
    if (gid == 0)            g_njobs = 0;
    if (blockIdx.x < 147) {
        int k = blockIdx.x, c = threadIdx.x;
        g_Wt[k*OC + c] = Wc[c*147 + k];
    }
    // hi/lo tf32 weight fragments: idx = (((ct*19+s)*8+Ml)*32+lane)*4+reg
    if (gid < 2*NFRAG) {
        int reg  = gid & 3;
        int lane = (gid >> 2) & 31;
        int Ml   = (gid >> 7) & 7;
        int ct   = gid / NFRAG;
        int s    = (gid - ct*NFRAG) >> 10;
        int oc = ct*128 + Ml*16 + (lane >> 2) + (reg & 1)*8;
        int k  = s*8 + (lane & 3) + (reg >> 1)*4;
        float wv = (k < 147) ? Wc[oc*147 + k] : 0.f;
        float hi = tf32r(wv);
        g_WfragHi[gid] = hi;
        g_WfragLo[gid] = tf32r(wv - hi);
    }
    if (blockIdx.x == 159) {
        // labels dtype probe: first 1200 int64 words == extent of an int32 buffer
        // of 2400 elems (never OOB). Real int64 labels all lie in [0,91).
        __shared__ int bad;
        if (threadIdx.x == 0) bad = 0;
        __syncthreads();
        for (int i = threadIdx.x; i < 1200; i += 256) {
            long long v = lab[i];
            if (v < 0 || v >= 91) bad = 1;
        }
        __syncthreads();
        if (threadIdx.x == 0) g_lab64 = bad ? 0 : 1;
    }
}

// ---------------------------------------------------------------- top-k: one warp per batch
__global__ void topk_kernel(const float* __restrict__ boxes,
                            const float* __restrict__ scores,
                            const void* __restrict__ labels_raw,
                            float* __restrict__ out) {
    int b = blockIdx.x;
    int t = threadIdx.x;
    int lab64 = g_lab64;
    const int*       l32 = (const int*)labels_raw;
    const long long* l64 = (const long long*)labels_raw;

    float v[10];
    #pragma unroll
    for (int r = 0; r < 10; r++) {
        int i = t + 32*r;
        float s = -INFINITY;
        if (i < NBOX) {
            long long l = lab64 ? l64[b*NBOX + i] : (long long)l32[b*NBOX + i];
            bool veh = (l==2)||(l==3)||(l==4)||(l==6)||(l==8);
            float sc = scores[b*NBOX + i];
            if (veh && sc > 0.8f) s = sc;
        }
        v[r] = s;
    }
    for (int k = 0; k < TOPK; k++) {
        float bv = -INFINITY; int bi = 0x7fffffff;
        #pragma unroll
        for (int r = 0; r < 10; r++) {
            int i = t + 32*r;
            if (v[r] > bv) { bv = v[r]; bi = i; }
        }
        #pragma unroll
        for (int o = 16; o > 0; o >>= 1) {
            float ov = __shfl_down_sync(0xffffffffu, bv, o);
            int   oi = __shfl_down_sync(0xffffffffu, bi, o);
            if (ov > bv || (ov == bv && oi < bi)) { bv = ov; bi = oi; }
        }
        bv = __shfl_sync(0xffffffffu, bv, 0);
        bi = __shfl_sync(0xffffffffu, bi, 0);
        bool valid = (bv != -INFINITY);
        if (valid && (bi & 31) == t) {
            int r = bi >> 5;
            #pragma unroll
            for (int rr = 0; rr < 10; rr++) if (rr == r) v[rr] = -INFINITY;
        }
        if (t == 0) {
            float b0=0.f,b1=0.f,b2=0.f,b3=0.f;
            if (valid) {
                const float* bp = boxes + (b*NBOX + bi)*4;
                b0=bp[0]; b1=bp[1]; b2=bp[2]; b3=bp[3];
            }
            int bk = b*TOPK + k;
            out[OBJ_OFF + bk*4+0] = b0;
            out[OBJ_OFF + bk*4+1] = b1;
            out[OBJ_OFF + bk*4+2] = b2;
            out[OBJ_OFF + bk*4+3] = b3;
            out[VALID_OFF + bk]   = valid ? 1.0f : 0.0f;
            if (valid && b2 > b0 && b3 > b1) {
                int pos = atomicAdd(&g_njobs, 1);
                g_job_box[pos*4+0]=b0; g_job_box[pos*4+1]=b1;
                g_job_box[pos*4+2]=b2; g_job_box[pos*4+3]=b3;
                g_job_b[pos]  = b;
                g_job_bk[pos] = bk;
            }
        }
    }
}

// ---------------------------------------------------------------- RoIAlign (normalized on the fly)
__global__ void sample_kernel(const float* __restrict__ x) {
    int j = blockIdx.x;
    if (j >= g_njobs) return;
    int b = g_job_b[j];
    float bx0 = g_job_box[j*4+0], by0 = g_job_box[j*4+1];
    float bx1 = g_job_box[j*4+2], by1 = g_job_box[j*4+3];
    for (int idx = threadIdx.x; idx < 3*CROPS*CROPS; idx += blockDim.x) {
        int c  = idx >> 12;
        int rem = idx & 4095;
        int yi = rem >> 6, xi = rem & 63;
        float ys = by0 + (yi + 0.5f)*(1.0f/CROPS)*(by1 - by0);
        float xs = bx0 + (xi + 0.5f)*(1.0f/CROPS)*(bx1 - bx0);
        float yf = floorf(ys), xf = floorf(xs);
        float wy = ys - yf,  wx = xs - xf;
        int y0 = min(max((int)yf, 0), HW-1); int y1 = min(y0+1, HW-1);
        int x0 = min(max((int)xf, 0), HW-1); int x1 = min(x0+1, HW-1);
        const float* img = x + ((long)b*3 + c)*HW*HW;
        float m = c_mean[c], is = c_istd[c];
        float Ia = (img[y0*HW + x0]-m)*is, Ib = (img[y0*HW + x1]-m)*is;
        float Ic = (img[y1*HW + x0]-m)*is, Id = (img[y1*HW + x1]-m)*is;
        g_crops[j*(3*CROPS*CROPS) + idx] =
            Ia*(1.f-wy)*(1.f-wx) + Ib*(1.f-wy)*wx + Ic*wy*(1.f-wx) + Id*wy*wx;
    }
}

// ---------------------------------------------------------------- unified conv
// bx < FULL_BLOCKS: tf32 mma fullframe tile (128 oc x 64 px) — small tile for
// 3 blocks/SM so build phases overlap other blocks' MMA phases.
// else: scalar FFMA2 crop tile (exact fp32).
__global__ void __launch_bounds__(256, 3) conv_kernel(const float* __restrict__ x,
                                                      const float* __restrict__ bc) {
    extern __shared__ char smc[];
    int t = threadIdx.x;
    int w = t >> 5, lane = t & 31;
    int bx = blockIdx.x;

    if (bx < FULL_BLOCKS) {
        float* smB = (float*)smc;
        int4*  dec = (int4*)(smc + DEC_OFF);
        int ocg = w & 3, pxg = w >> 2;
        int ct = bx & 1;
        int ph = (bx >> 1) & 1;          // px half: 0 -> px 0..63, 1 -> 64..127
        int oy = (bx >> 2) & 127, b = bx >> 9;
        int c0 = ct*128;

        // decode table: k -> {flat_off, ky, kx, cin}
        if (t < 152) {
            int k = t;
            int cin = k/49; int rr = k - cin*49;
            int ky = rr/7;  int kx = rr - ky*7;
            if (k >= 147) { cin = 0; ky = 0; kx = 0; }
            dec[t] = make_int4(cin*262144 + ky*512 + kx - 1, ky, kx, cin);
        }
        __syncthreads();

        // build fragment-packed im2col for 64 px (rna-rounded to tf32)
        // warp = (wq = px quadrant of 16, wh = k-step parity)
        {
            int wq = w & 3, wh = w >> 2;
            int k0  = lane & 3;
            int px0 = wq*16 + (lane >> 2);         // 0..63 local
            int iyb = 4*oy - 1;
            int iyb512 = iyb*512;
            const float* xb = x + (long)b*3*262144;
            #pragma unroll 2
            for (int it = wh; it < KSTEPS; it += 2) {
                float v[4];
                #pragma unroll
                for (int e = 0; e < 4; e++) {
                    int k  = it*8 + k0 + (e & 1)*4;
                    int px = ph*64 + px0 + (e >> 1)*8;   // global px 0..127
                    float val = 0.f;
                    if (k < 147) {
                        int4 dc = dec[k];
                        int iy = iyb + dc.y;
                        int ix = 4*px - 1 + dc.z;
                        if ((unsigned)iy < 512u && (unsigned)ix < 512u)
                            val = (xb[dc.x + iyb512 + 4*px] - c_mean[dc.w])*c_istd[dc.w];
                    }
                    v[e] = tf32r(val);
                }
                float4* dst = (float4*)smB + (it*4 + wq)*32 + lane;
                *dst = make_float4(v[0], v[1], v[2], v[3]);
            }
        }
        __syncthreads();

        float d[2][4][4];
        #pragma unroll
        for (int mt = 0; mt < 2; mt++)
            #pragma unroll
            for (int nt = 0; nt < 4; nt++)
                #pragma unroll
                for (int r = 0; r < 4; r++) d[mt][nt][r] = 0.f;

        const uint4* aH = (const uint4*)g_WfragHi + ((ct*KSTEPS)*8 + ocg*2)*32 + lane;
        const uint4* aL = (const uint4*)g_WfragLo + ((ct*KSTEPS)*8 + ocg*2)*32 + lane;
        const uint4* bf = (const uint4*)smB + (pxg*2)*32 + lane;
        uint4 nh0 = aH[0], nh1 = aH[32];
        uint4 nl0 = aL[0], nl1 = aL[32];
        #pragma unroll 1
        for (int s = 0; s < KSTEPS; s++) {
            uint4 h0 = nh0, h1 = nh1, l0 = nl0, l1 = nl1;
            int sn = (s + 1 < KSTEPS) ? s + 1 : s;
            nh0 = aH[(sn*8)*32];  nh1 = aH[(sn*8 + 1)*32];
            nl0 = aL[(sn*8)*32];  nl1 = aL[(sn*8 + 1)*32];
            uint4 b0 = bf[(s*4)*32];
            uint4 b1 = bf[(s*4 + 1)*32];
            const uint32_t* ph0 = (const uint32_t*)&h0;
            const uint32_t* ph1 = (const uint32_t*)&h1;
            const uint32_t* pl0 = (const uint32_t*)&l0;
            const uint32_t* pl1 = (const uint32_t*)&l1;
            // 8 independent hi-MMAs ...
            mma_tf32(d[0][0], ph0, b0.x, b0.y);
            mma_tf32(d[0][1], ph0, b0.z, b0.w);
            mma_tf32(d[0][2], ph0, b1.x, b1.y);
            mma_tf32(d[0][3], ph0, b1.z, b1.w);
            mma_tf32(d[1][0], ph1, b0.x, b0.y);
            mma_tf32(d[1][1], ph1, b0.z, b0.w);
            mma_tf32(d[1][2], ph1, b1.x, b1.y);
            mma_tf32(d[1][3], ph1, b1.z, b1.w);
            // ... then 8 lo-MMAs
            mma_tf32(d[0][0], pl0, b0.x, b0.y);
            mma_tf32(d[0][1], pl0, b0.z, b0.w);
            mma_tf32(d[0][2], pl0, b1.x, b1.y);
            mma_tf32(d[0][3], pl0, b1.z, b1.w);
            mma_tf32(d[1][0], pl1, b0.x, b0.y);
            mma_tf32(d[1][1], pl1, b0.z, b0.w);
            mma_tf32(d[1][2], pl1, b1.x, b1.y);
            mma_tf32(d[1][3], pl1, b1.z, b1.w);
        }

        // epilogue: bias + relu + pool over px, atomic accumulate
        #pragma unroll
        for (int mt = 0; mt < 2; mt++) {
            int oc_r0 = c0 + ocg*32 + mt*16 + (lane >> 2);
            float bias0 = bc[oc_r0];
            float bias1 = bc[oc_r0 + 8];
            float s0 = 0.f, s1 = 0.f;
            #pragma unroll
            for (int nt = 0; nt < 4; nt++) {
                s0 += fmaxf(d[mt][nt][0] + bias0, 0.f) + fmaxf(d[mt][nt][1] + bias0, 0.f);
                s1 += fmaxf(d[mt][nt][2] + bias1, 0.f) + fmaxf(d[mt][nt][3] + bias1, 0.f);
            }
            s0 += __shfl_xor_sync(0xffffffffu, s0, 1);
            s0 += __shfl_xor_sync(0xffffffffu, s0, 2);
            s1 += __shfl_xor_sync(0xffffffffu, s1, 1);
            s1 += __shfl_xor_sync(0xffffffffu, s1, 2);
            if ((lane & 3) == 0) {
                atomicAdd(&g_pooled_full[b*OC + oc_r0],     s0);
                atomicAdd(&g_pooled_full[b*OC + oc_r0 + 8], s1);
            }
        }
    } else {
        // ------------- crop: half (8 out-rows = 128 px) x 128 channels, exact fp32
        float* sm = (float*)smc;
        int pxg = lane, cg = w;
        int cx2 = bx - FULL_BLOCKS;
        int ct = cx2 & 1; int half = (cx2 >> 1) & 1; int j = cx2 >> 2;
        if (j >= g_njobs) return;
        int c0 = ct*128;
        const float* crop = g_crops + (long)j*(3*CROPS*CROPS);
        int iy0 = half*32 - 1;
        for (int s = t; s < 105*67; s += 256) {
            int row = s / 67; int p = s - row*67;
            int cin = row / 35; int iyl = row - cin*35;
            int cy = iy0 + iyl, cxx = p - 1;
            float v = 0.f;
            if ((unsigned)cy < 64u && (unsigned)cxx < 64u)
                v = crop[(cin*64 + cy)*64 + cxx];
            sm[row*84 + (p&3)*18 + (p>>2)] = v;
        }
        __syncthreads();

        int rowoff[4];
        #pragma unroll
        for (int m = 0; m < 4; m++) {
            int px = pxg + 32*m;
            rowoff[m] = (px >> 4)*4*84 + (px & 15);
        }
        u64 acc[4][8];
        {
            const u64* b2 = (const u64*)(bc + c0 + cg*16);
            #pragma unroll
            for (int i = 0; i < 8; i++) {
                u64 bb = b2[i];
                acc[0][i]=bb; acc[1][i]=bb; acc[2][i]=bb; acc[3][i]=bb;
            }
        }
        const float* wbase = g_Wt + c0 + cg*16;
        for (int cin = 0; cin < 3; cin++) {
            const float* plc = sm + cin*35*84;
            const float* wc  = wbase + cin*49*OC;
            #pragma unroll
            for (int ky = 0; ky < 7; ky++) {
                #pragma unroll
                for (int kx = 0; kx < 7; kx++) {
                    const float* pl = plc + ky*84 + (kx&3)*18 + (kx>>2);
                    float a0 = pl[rowoff[0]], a1 = pl[rowoff[1]];
                    float a2 = pl[rowoff[2]], a3 = pl[rowoff[3]];
                    const ulonglong2* wp = (const ulonglong2*)(wc + (ky*7+kx)*OC);
                    ulonglong2 wA = wp[0], wB = wp[1], wC = wp[2], wD = wp[3];
                    u64 dd;
                    dd = dup2(a0);
                    ffma2(acc[0][0],dd,wA.x); ffma2(acc[0][1],dd,wA.y); ffma2(acc[0][2],dd,wB.x); ffma2(acc[0][3],dd,wB.y);
                    ffma2(acc[0][4],dd,wC.x); ffma2(acc[0][5],dd,wC.y); ffma2(acc[0][6],dd,wD.x); ffma2(acc[0][7],dd,wD.y);
                    dd = dup2(a1);
                    ffma2(acc[1][0],dd,wA.x); ffma2(acc[1][1],dd,wA.y); ffma2(acc[1][2],dd,wB.x); ffma2(acc[1][3],dd,wB.y);
                    ffma2(acc[1][4],dd,wC.x); ffma2(acc[1][5],dd,wC.y); ffma2(acc[1][6],dd,wD.x); ffma2(acc[1][7],dd,wD.y);
                    dd = dup2(a2);
                    ffma2(acc[2][0],dd,wA.x); ffma2(acc[2][1],dd,wA.y); ffma2(acc[2][2],dd,wB.x); ffma2(acc[2][3],dd,wB.y);
                    ffma2(acc[2][4],dd,wC.x); ffma2(acc[2][5],dd,wC.y); ffma2(acc[2][6],dd,wD.x); ffma2(acc[2][7],dd,wD.y);
                    dd = dup2(a3);
                    ffma2(acc[3][0],dd,wA.x); ffma2(acc[3][1],dd,wA.y); ffma2(acc[3][2],dd,wB.x); ffma2(acc[3][3],dd,wB.y);
                    ffma2(acc[3][4],dd,wC.x); ffma2(acc[3][5],dd,wC.y); ffma2(acc[3][6],dd,wD.x); ffma2(acc[3][7],dd,wD.y);
                }
            }
        }
        #pragma unroll
        for (int i = 0; i < 8; i++) {
            float s0 = 0.f, s1 = 0.f;
            #pragma unroll
            for (int m = 0; m < 4; m++) {
                float lo, hi; unpack2(acc[m][i], lo, hi);
                s0 += fmaxf(lo, 0.f); s1 += fmaxf(hi, 0.f);
            }
            #pragma unroll
            for (int o = 16; o > 0; o >>= 1) {
                s0 += __shfl_down_sync(0xffffffffu, s0, o);
                s1 += __shfl_down_sync(0xffffffffu, s1, o);
            }
            if (pxg == 0) {
                atomicAdd(&g_pooled_crop[j*OC + c0 + cg*16 + 2*i],     s0);
                atomicAdd(&g_pooled_crop[j*OC + c0 + cg*16 + 2*i + 1], s1);
            }
        }
    }
}

// ---------------------------------------------------------------- unified FC
__global__ void __launch_bounds__(256) fc_kernel(const float* __restrict__ Wf,
                                                 const float* __restrict__ bf,
                                                 float* __restrict__ out) {
    int y = blockIdx.y, t = threadIdx.x;
    int o = blockIdx.x*256 + t;
    __shared__ float sp[8*OC];
    if (y == 0) {
        for (int s = t; s < BATCH*OC; s += 256)
            sp[s] = g_pooled_full[s] * (1.0f/16384.0f);
        __syncthreads();
        float acc[8] = {0.f,0.f,0.f,0.f,0.f,0.f,0.f,0.f};
        for (int c = 0; c < OC; c++) {
            float w = Wf[(long)c*FCO + o];
            #pragma unroll
            for (int b2 = 0; b2 < 8; b2++) acc[b2] += sp[b2*OC + c] * w;
        }
        float bias = bf[o];
        #pragma unroll
        for (int b2 = 0; b2 < 8; b2++)
            out[FULL_OFF + b2*FCO + o] = acc[b2] + bias;
    } else {
        int nj = g_njobs;
        int j0 = (y - 1)*8;
        if (j0 >= nj) return;
        for (int s = t; s < 8*OC; s += 256) {
            int jj = s >> 8; int c = s & 255;
            int j = j0 + jj;
            sp[s] = (j < nj) ? g_pooled_crop[j*OC + c] * (1.0f/256.0f) : 0.f;
        }
        __syncthreads();
        float acc[8] = {0.f,0.f,0.f,0.f,0.f,0.f,0.f,0.f};
        for (int c = 0; c < OC; c++) {
            float w = Wf[(long)c*FCO + o];
            #pragma unroll
            for (int jj = 0; jj < 8; jj++) acc[jj] += sp[jj*OC + c] * w;
        }
        float bias = bf[o];
        #pragma unroll
        for (int jj = 0; jj < 8; jj++) {
            int j = j0 + jj;
            if (j < nj)
                out[FEAT_OFF + (long)g_job_bk[j]*FCO + o] = acc[jj] + bias;
        }
    }
}

// ---------------------------------------------------------------- launch
extern "C" void kernel_launch(void* const* d_in, const int* in_sizes, int n_in,
                              void* d_out, int out_size) {
    const float* x      = (const float*)d_in[0];
    const float* boxes  = (const float*)d_in[1];
    const float* scores = (const float*)d_in[2];
    const void*  labels = d_in[3];
    const float* Wc     = (const float*)d_in[4];
    const float* bc     = (const float*)d_in[5];
    const float* Wf     = (const float*)d_in[6];
    const float* bf     = (const float*)d_in[7];
    float* out = (float*)d_out;

    cudaFuncSetAttribute(conv_kernel, cudaFuncAttributeMaxDynamicSharedMemorySize, CONV_SMEM);

    prep_kernel<<<320, 256>>>(Wc, (const long long*)labels);
    topk_kernel<<<BATCH, 32>>>(boxes, scores, labels, out);
    cudaMemsetAsync(out + FEAT_OFF, 0, (size_t)BATCH*TOPK*FCO*sizeof(float));
    sample_kernel<<<BATCH*TOPK, 256>>>(x);
    conv_kernel<<<FULL_BLOCKS + CROP_BLOCKS, 256, CONV_SMEM>>>(x, bc);
    fc_kernel<<<dim3(16, 21), 256>>>(Wf, bf, out);
}

// round 12
// speedup vs baseline: 1.8677x; 1.8677x over previous
#include <cuda_runtime.h>
#include <math.h>
#include <stdint.h>

typedef unsigned long long u64;

#define BATCH 8
#define NBOX  300
#define TOPK  20
#define HW    512
#define CROPS 64
#define OC    256
#define FCO   4096

// d_out layout (floats): Objects[8,20,4] | Object_features[8,20,4096] | valid[8,20] | fullframe[8,4096]
#define OBJ_OFF   0
#define FEAT_OFF  640
#define VALID_OFF 656000
#define FULL_OFF  656160

#define KSTEPS 19                      // 147 -> 152 (19 k-steps of 8)
#define NFRAG  (KSTEPS*8*32*4)         // 19456 floats per ct
#define BSMEM_BYTES (KSTEPS*8*32*16)   // 77824 B fragment-packed im2col
#define DEC_OFF  BSMEM_BYTES           // int4[152] decode table
#define CONV_SMEM (BSMEM_BYTES + 152*16)   // 80256 B
#define FULL_BLOCKS 2048
#define CROP_BLOCKS (BATCH*TOPK*4)     // job * 2 halves * 2 ct

__constant__ float c_mean[3] = {0.485f, 0.456f, 0.406f};
__constant__ float c_istd[3] = {1.0f/0.229f, 1.0f/0.224f, 1.0f/0.225f};

__device__ float g_pooled_full[BATCH*OC];
__device__ float g_pooled_crop[BATCH*TOPK*OC];
__device__ float g_crops[BATCH*TOPK*3*CROPS*CROPS];
__device__ __align__(16) float g_Wt[147*OC];         // [k][oc] for scalar crop conv
__device__ __align__(16) float g_WfragHi[2*NFRAG];   // rna-rounded tf32 weight fragments
__device__ float g_job_box[BATCH*TOPK*4];
__device__ int   g_job_b[BATCH*TOPK];
__device__ int   g_job_bk[BATCH*TOPK];
__device__ int   g_njobs;
__device__ int   g_lab64;

// ---------------------------------------------------------------- helpers
__device__ __forceinline__ void ffma2(u64 &d, u64 a, u64 b) {
    asm("fma.rn.f32x2 %0, %1, %2, %0;" : "+l"(d) : "l"(a), "l"(b));
}
__device__ __forceinline__ u64 dup2(float a) {
    u64 r; asm("mov.b64 %0, {%1, %1};" : "=l"(r) : "f"(a)); return r;
}
__device__ __forceinline__ void unpack2(u64 v, float &lo, float &hi) {
    asm("mov.b64 {%0, %1}, %2;" : "=f"(lo), "=f"(hi) : "l"(v));
}
__device__ __forceinline__ float tf32r(float a) {
    uint32_t u; asm("cvt.rna.tf32.f32 %0, %1;" : "=r"(u) : "f"(a));
    return __uint_as_float(u);
}
__device__ __forceinline__ void mma_tf32(float* d, const uint32_t* a, uint32_t b0, uint32_t b1) {
    asm volatile(
        "mma.sync.aligned.m16n8k8.row.col.f32.tf32.tf32.f32 "
        "{%0,%1,%2,%3}, {%4,%5,%6,%7}, {%8,%9}, {%0,%1,%2,%3};"
        : "+f"(d[0]), "+f"(d[1]), "+f"(d[2]), "+f"(d[3])
        : "r"(a[0]), "r"(a[1]), "r"(a[2]), "r"(a[3]), "r"(b0), "r"(b1));
}

// ---------------------------------------------------------------- prep
__global__ void prep_kernel(const float* __restrict__ Wc,
                            const long long* __restrict__ lab) {
    int gid = blockIdx.x*256 + threadIdx.x;
    if (gid < BATCH*OC)      g_pooled_full[gid] = 0.f;
    if (gid < BATCH*TOPK*OC) g_pooled_crop[gid] = 0.f;
    if (gid == 0)            g_njobs = 0;
    if (blockIdx.x < 147) {
        int k = blockIdx.x, c = threadIdx.x;
        g_Wt[k*OC + c] = Wc[c*147 + k];
    }
    // rna tf32 weight fragments: idx = (((ct*19+s)*8+Ml)*32+lane)*4+reg
    if (gid < 2*NFRAG) {
        int reg  = gid & 3;
        int lane = (gid >> 2) & 31;
        int Ml   = (gid >> 7) & 7;
        int ct   = gid / NFRAG;
        int s    = (gid - ct*NFRAG) >> 10;
        int oc = ct*128 + Ml*16 + (lane >> 2) + (reg & 1)*8;
        int k  = s*8 + (lane & 3) + (reg >> 1)*4;
        float wv = (k < 147) ? Wc[oc*147 + k] : 0.f;
        g_WfragHi[gid] = tf32r(wv);
    }
    if (blockIdx.x == 159) {
        // labels dtype probe: first 1200 int64 words == extent of an int32 buffer
        // of 2400 elems (never OOB). Real int64 labels all lie in [0,91).
        __shared__ int bad;
        if (threadIdx.x == 0) bad = 0;
        __syncthreads();
        for (int i = threadIdx.x; i < 1200; i += 256) {
            long long v = lab[i];
            if (v < 0 || v >= 91) bad = 1;
        }
        __syncthreads();
        if (threadIdx.x == 0) g_lab64 = bad ? 0 : 1;
    }
}

// ---------------------------------------------------------------- top-k: one warp per batch
__global__ void topk_kernel(const float* __restrict__ boxes,
                            const float* __restrict__ scores,
                            const void* __restrict__ labels_raw,
                            float* __restrict__ out) {
    int b = blockIdx.x;
    int t = threadIdx.x;
    int lab64 = g_lab64;
    const int*       l32 = (const int*)labels_raw;
    const long long* l64 = (const long long*)labels_raw;

    float v[10];
    #pragma unroll
    for (int r = 0; r < 10; r++) {
        int i = t + 32*r;
        float s = -INFINITY;
        if (i < NBOX) {
            long long l = lab64 ? l64[b*NBOX + i] : (long long)l32[b*NBOX + i];
            bool veh = (l==2)||(l==3)||(l==4)||(l==6)||(l==8);
            float sc = scores[b*NBOX + i];
            if (veh && sc > 0.8f) s = sc;
        }
        v[r] = s;
    }
    for (int k = 0; k < TOPK; k++) {
        float bv = -INFINITY; int bi = 0x7fffffff;
        #pragma unroll
        for (int r = 0; r < 10; r++) {
            int i = t + 32*r;
            if (v[r] > bv) { bv = v[r]; bi = i; }
        }
        #pragma unroll
        for (int o = 16; o > 0; o >>= 1) {
            float ov = __shfl_down_sync(0xffffffffu, bv, o);
            int   oi = __shfl_down_sync(0xffffffffu, bi, o);
            if (ov > bv || (ov == bv && oi < bi)) { bv = ov; bi = oi; }
        }
        bv = __shfl_sync(0xffffffffu, bv, 0);
        bi = __shfl_sync(0xffffffffu, bi, 0);
        bool valid = (bv != -INFINITY);
        if (valid && (bi & 31) == t) {
            int r = bi >> 5;
            #pragma unroll
            for (int rr = 0; rr < 10; rr++) if (rr == r) v[rr] = -INFINITY;
        }
        if (t == 0) {
            float b0=0.f,b1=0.f,b2=0.f,b3=0.f;
            if (valid) {
                const float* bp = boxes + (b*NBOX + bi)*4;
                b0=bp[0]; b1=bp[1]; b2=bp[2]; b3=bp[3];
            }
            int bk = b*TOPK + k;
            out[OBJ_OFF + bk*4+0] = b0;
            out[OBJ_OFF + bk*4+1] = b1;
            out[OBJ_OFF + bk*4+2] = b2;
            out[OBJ_OFF + bk*4+3] = b3;
            out[VALID_OFF + bk]   = valid ? 1.0f : 0.0f;
            if (valid && b2 > b0 && b3 > b1) {
                int pos = atomicAdd(&g_njobs, 1);
                g_job_box[pos*4+0]=b0; g_job_box[pos*4+1]=b1;
                g_job_box[pos*4+2]=b2; g_job_box[pos*4+3]=b3;
                g_job_b[pos]  = b;
                g_job_bk[pos] = bk;
            }
        }
    }
}

// ---------------------------------------------------------------- RoIAlign (normalized on the fly)
__global__ void sample_kernel(const float* __restrict__ x) {
    int j = blockIdx.x;
    if (j >= g_njobs) return;
    int b = g_job_b[j];
    float bx0 = g_job_box[j*4+0], by0 = g_job_box[j*4+1];
    float bx1 = g_job_box[j*4+2], by1 = g_job_box[j*4+3];
    for (int idx = threadIdx.x; idx < 3*CROPS*CROPS; idx += blockDim.x) {
        int c  = idx >> 12;
        int rem = idx & 4095;
        int yi = rem >> 6, xi = rem & 63;
        float ys = by0 + (yi + 0.5f)*(1.0f/CROPS)*(by1 - by0);
        float xs = bx0 + (xi + 0.5f)*(1.0f/CROPS)*(bx1 - bx0);
        float yf = floorf(ys), xf = floorf(xs);
        float wy = ys - yf,  wx = xs - xf;
        int y0 = min(max((int)yf, 0), HW-1); int y1 = min(y0+1, HW-1);
        int x0 = min(max((int)xf, 0), HW-1); int x1 = min(x0+1, HW-1);
        const float* img = x + ((long)b*3 + c)*HW*HW;
        float m = c_mean[c], is = c_istd[c];
        float Ia = (img[y0*HW + x0]-m)*is, Ib = (img[y0*HW + x1]-m)*is;
        float Ic = (img[y1*HW + x0]-m)*is, Id = (img[y1*HW + x1]-m)*is;
        g_crops[j*(3*CROPS*CROPS) + idx] =
            Ia*(1.f-wy)*(1.f-wx) + Ib*(1.f-wy)*wx + Ic*wy*(1.f-wx) + Id*wy*wx;
    }
}

// ---------------------------------------------------------------- unified conv
// bx < FULL_BLOCKS: tf32 mma fullframe tile (128 oc x 128 px), rna weights (single pass).
// else: scalar FFMA2 crop tile (exact fp32).
__global__ void __launch_bounds__(256, 2) conv_kernel(const float* __restrict__ x,
                                                      const float* __restrict__ bc) {
    extern __shared__ char smc[];
    int t = threadIdx.x;
    int w = t >> 5, lane = t & 31;
    int bx = blockIdx.x;

    if (bx < FULL_BLOCKS) {
        float* smB = (float*)smc;
        int4*  dec = (int4*)(smc + DEC_OFF);
        int ocg = w & 3, pxg = w >> 2;
        int ct = bx & 1, tile = bx >> 1;
        int oy = tile & 127, b = tile >> 7;
        int c0 = ct*128;

        // decode table: k -> {flat_off, ky, kx, cin}
        if (t < 152) {
            int k = t;
            int cin = k/49; int rr = k - cin*49;
            int ky = rr/7;  int kx = rr - ky*7;
            if (k >= 147) { cin = 0; ky = 0; kx = 0; }
            dec[t] = make_int4(cin*262144 + ky*512 + kx - 1, ky, kx, cin);
        }
        __syncthreads();

        // build fragment-packed im2col (rna-rounded to tf32)
        {
            int k0  = lane & 3;
            int px0 = w*16 + (lane >> 2);
            int iyb = 4*oy - 1;
            int iyb512 = iyb*512;
            const float* xb = x + (long)b*3*262144;
            #pragma unroll 4
            for (int it = 0; it < KSTEPS; it++) {
                float v[4];
                #pragma unroll
                for (int e = 0; e < 4; e++) {
                    int k  = it*8 + k0 + (e & 1)*4;
                    int px = px0 + (e >> 1)*8;
                    float val = 0.f;
                    if (k < 147) {
                        int4 dc = dec[k];
                        int iy = iyb + dc.y;
                        int ix = 4*px - 1 + dc.z;
                        if ((unsigned)iy < 512u && (unsigned)ix < 512u)
                            val = (xb[dc.x + iyb512 + 4*px] - c_mean[dc.w])*c_istd[dc.w];
                    }
                    v[e] = tf32r(val);
                }
                float4* dst = (float4*)smB + (it*8 + w)*32 + lane;
                *dst = make_float4(v[0], v[1], v[2], v[3]);
            }
        }
        __syncthreads();

        float d[2][8][4];
        #pragma unroll
        for (int mt = 0; mt < 2; mt++)
            #pragma unroll
            for (int nt = 0; nt < 8; nt++)
                #pragma unroll
                for (int r = 0; r < 4; r++) d[mt][nt][r] = 0.f;

        const uint4* aH = (const uint4*)g_WfragHi + ((ct*KSTEPS)*8 + ocg*2)*32 + lane;
        const uint4* bf = (const uint4*)smB + (pxg*4)*32 + lane;
        uint4 nh0 = aH[0], nh1 = aH[32];
        #pragma unroll 1
        for (int s = 0; s < KSTEPS; s++) {
            uint4 h0 = nh0, h1 = nh1;
            int sn = (s + 1 < KSTEPS) ? s + 1 : s;
            nh0 = aH[(sn*8)*32];  nh1 = aH[(sn*8 + 1)*32];
            uint4 b0 = bf[(s*8)*32];
            uint4 b1 = bf[(s*8 + 1)*32];
            uint4 b2 = bf[(s*8 + 2)*32];
            uint4 b3 = bf[(s*8 + 3)*32];
            const uint32_t* ph0 = (const uint32_t*)&h0;
            const uint32_t* ph1 = (const uint32_t*)&h1;
            mma_tf32(d[0][0], ph0, b0.x, b0.y);
            mma_tf32(d[0][1], ph0, b0.z, b0.w);
            mma_tf32(d[0][2], ph0, b1.x, b1.y);
            mma_tf32(d[0][3], ph0, b1.z, b1.w);
            mma_tf32(d[0][4], ph0, b2.x, b2.y);
            mma_tf32(d[0][5], ph0, b2.z, b2.w);
            mma_tf32(d[0][6], ph0, b3.x, b3.y);
            mma_tf32(d[0][7], ph0, b3.z, b3.w);
            mma_tf32(d[1][0], ph1, b0.x, b0.y);
            mma_tf32(d[1][1], ph1, b0.z, b0.w);
            mma_tf32(d[1][2], ph1, b1.x, b1.y);
            mma_tf32(d[1][3], ph1, b1.z, b1.w);
            mma_tf32(d[1][4], ph1, b2.x, b2.y);
            mma_tf32(d[1][5], ph1, b2.z, b2.w);
            mma_tf32(d[1][6], ph1, b3.x, b3.y);
            mma_tf32(d[1][7], ph1, b3.z, b3.w);
        }

        // epilogue: bias + relu + pool over px, atomic accumulate
        #pragma unroll
        for (int mt = 0; mt < 2; mt++) {
            int oc_r0 = c0 + ocg*32 + mt*16 + (lane >> 2);
            float bias0 = bc[oc_r0];
            float bias1 = bc[oc_r0 + 8];
            float s0 = 0.f, s1 = 0.f;
            #pragma unroll
            for (int nt = 0; nt < 8; nt++) {
                s0 += fmaxf(d[mt][nt][0] + bias0, 0.f) + fmaxf(d[mt][nt][1] + bias0, 0.f);
                s1 += fmaxf(d[mt][nt][2] + bias1, 0.f) + fmaxf(d[mt][nt][3] + bias1, 0.f);
            }
            s0 += __shfl_xor_sync(0xffffffffu, s0, 1);
            s0 += __shfl_xor_sync(0xffffffffu, s0, 2);
            s1 += __shfl_xor_sync(0xffffffffu, s1, 1);
            s1 += __shfl_xor_sync(0xffffffffu, s1, 2);
            if ((lane & 3) == 0) {
                atomicAdd(&g_pooled_full[b*OC + oc_r0],     s0);
                atomicAdd(&g_pooled_full[b*OC + oc_r0 + 8], s1);
            }
        }
    } else {
        // ------------- crop: half (8 out-rows = 128 px) x 128 channels, exact fp32
        float* sm = (float*)smc;
        int pxg = lane, cg = w;
        int cx2 = bx - FULL_BLOCKS;
        int ct = cx2 & 1; int half = (cx2 >> 1) & 1; int j = cx2 >> 2;
        if (j >= g_njobs) return;
        int c0 = ct*128;
        const float* crop = g_crops + (long)j*(3*CROPS*CROPS);
        int iy0 = half*32 - 1;
        for (int s = t; s < 105*67; s += 256) {
            int row = s / 67; int p = s - row*67;
            int cin = row / 35; int iyl = row - cin*35;
            int cy = iy0 + iyl, cxx = p - 1;
            float v = 0.f;
            if ((unsigned)cy < 64u && (unsigned)cxx < 64u)
                v = crop[(cin*64 + cy)*64 + cxx];
            sm[row*84 + (p&3)*18 + (p>>2)] = v;
        }
        __syncthreads();

        int rowoff[4];
        #pragma unroll
        for (int m = 0; m < 4; m++) {
            int px = pxg + 32*m;
            rowoff[m] = (px >> 4)*4*84 + (px & 15);
        }
        u64 acc[4][8];
        {
            const u64* b2 = (const u64*)(bc + c0 + cg*16);
            #pragma unroll
            for (int i = 0; i < 8; i++) {
                u64 bb = b2[i];
                acc[0][i]=bb; acc[1][i]=bb; acc[2][i]=bb; acc[3][i]=bb;
            }
        }
        const float* wbase = g_Wt + c0 + cg*16;
        for (int cin = 0; cin < 3; cin++) {
            const float* plc = sm + cin*35*84;
            const float* wc  = wbase + cin*49*OC;
            #pragma unroll
            for (int ky = 0; ky < 7; ky++) {
                #pragma unroll
                for (int kx = 0; kx < 7; kx++) {
                    const float* pl = plc + ky*84 + (kx&3)*18 + (kx>>2);
                    float a0 = pl[rowoff[0]], a1 = pl[rowoff[1]];
                    float a2 = pl[rowoff[2]], a3 = pl[rowoff[3]];
                    const ulonglong2* wp = (const ulonglong2*)(wc + (ky*7+kx)*OC);
                    ulonglong2 wA = wp[0], wB = wp[1], wC = wp[2], wD = wp[3];
                    u64 dd;
                    dd = dup2(a0);
                    ffma2(acc[0][0],dd,wA.x); ffma2(acc[0][1],dd,wA.y); ffma2(acc[0][2],dd,wB.x); ffma2(acc[0][3],dd,wB.y);
                    ffma2(acc[0][4],dd,wC.x); ffma2(acc[0][5],dd,wC.y); ffma2(acc[0][6],dd,wD.x); ffma2(acc[0][7],dd,wD.y);
                    dd = dup2(a1);
                    ffma2(acc[1][0],dd,wA.x); ffma2(acc[1][1],dd,wA.y); ffma2(acc[1][2],dd,wB.x); ffma2(acc[1][3],dd,wB.y);
                    ffma2(acc[1][4],dd,wC.x); ffma2(acc[1][5],dd,wC.y); ffma2(acc[1][6],dd,wD.x); ffma2(acc[1][7],dd,wD.y);
                    dd = dup2(a2);
                    ffma2(acc[2][0],dd,wA.x); ffma2(acc[2][1],dd,wA.y); ffma2(acc[2][2],dd,wB.x); ffma2(acc[2][3],dd,wB.y);
                    ffma2(acc[2][4],dd,wC.x); ffma2(acc[2][5],dd,wC.y); ffma2(acc[2][6],dd,wD.x); ffma2(acc[2][7],dd,wD.y);
                    dd = dup2(a3);
                    ffma2(acc[3][0],dd,wA.x); ffma2(acc[3][1],dd,wA.y); ffma2(acc[3][2],dd,wB.x); ffma2(acc[3][3],dd,wB.y);
                    ffma2(acc[3][4],dd,wC.x); ffma2(acc[3][5],dd,wC.y); ffma2(acc[3][6],dd,wD.x); ffma2(acc[3][7],dd,wD.y);
                }
            }
        }
        #pragma unroll
        for (int i = 0; i < 8; i++) {
            float s0 = 0.f, s1 = 0.f;
            #pragma unroll
            for (int m = 0; m < 4; m++) {
                float lo, hi; unpack2(acc[m][i], lo, hi);
                s0 += fmaxf(lo, 0.f); s1 += fmaxf(hi, 0.f);
            }
            #pragma unroll
            for (int o = 16; o > 0; o >>= 1) {
                s0 += __shfl_down_sync(0xffffffffu, s0, o);
                s1 += __shfl_down_sync(0xffffffffu, s1, o);
            }
            if (pxg == 0) {
                atomicAdd(&g_pooled_crop[j*OC + c0 + cg*16 + 2*i],     s0);
                atomicAdd(&g_pooled_crop[j*OC + c0 + cg*16 + 2*i + 1], s1);
            }
        }
    }
}

// ---------------------------------------------------------------- unified FC
__global__ void __launch_bounds__(256) fc_kernel(const float* __restrict__ Wf,
                                                 const float* __restrict__ bf,
                                                 float* __restrict__ out) {
    int y = blockIdx.y, t = threadIdx.x;
    int o = blockIdx.x*256 + t;
    __shared__ float sp[8*OC];
    if (y == 0) {
        for (int s = t; s < BATCH*OC; s += 256)
            sp[s] = g_pooled_full[s] * (1.0f/16384.0f);
        __syncthreads();
        float acc[8] = {0.f,0.f,0.f,0.f,0.f,0.f,0.f,0.f};
        for (int c = 0; c < OC; c++) {
            float w = Wf[(long)c*FCO + o];
            #pragma unroll
            for (int b2 = 0; b2 < 8; b2++) acc[b2] += sp[b2*OC + c] * w;
        }
        float bias = bf[o];
        #pragma unroll
        for (int b2 = 0; b2 < 8; b2++)
            out[FULL_OFF + b2*FCO + o] = acc[b2] + bias;
    } else {
        int nj = g_njobs;
        int j0 = (y - 1)*8;
        if (j0 >= nj) return;
        for (int s = t; s < 8*OC; s += 256) {
            int jj = s >> 8; int c = s & 255;
            int j = j0 + jj;
            sp[s] = (j < nj) ? g_pooled_crop[j*OC + c] * (1.0f/256.0f) : 0.f;
        }
        __syncthreads();
        float acc[8] = {0.f,0.f,0.f,0.f,0.f,0.f,0.f,0.f};
        for (int c = 0; c < OC; c++) {
            float w = Wf[(long)c*FCO + o];
            #pragma unroll
            for (int jj = 0; jj < 8; jj++) acc[jj] += sp[jj*OC + c] * w;
        }
        float bias = bf[o];
        #pragma unroll
        for (int jj = 0; jj < 8; jj++) {
            int j = j0 + jj;
            if (j < nj)
                out[FEAT_OFF + (long)g_job_bk[j]*FCO + o] = acc[jj] + bias;
        }
    }
}

// ---------------------------------------------------------------- launch
extern "C" void kernel_launch(void* const* d_in, const int* in_sizes, int n_in,
                              void* d_out, int out_size) {
    const float* x      = (const float*)d_in[0];
    const float* boxes  = (const float*)d_in[1];
    const float* scores = (const float*)d_in[2];
    const void*  labels = d_in[3];
    const float* Wc     = (const float*)d_in[4];
    const float* bc     = (const float*)d_in[5];
    const float* Wf     = (const float*)d_in[6];
    const float* bf     = (const float*)d_in[7];
    float* out = (float*)d_out;

    cudaFuncSetAttribute(conv_kernel, cudaFuncAttributeMaxDynamicSharedMemorySize, CONV_SMEM);

    prep_kernel<<<320, 256>>>(Wc, (const long long*)labels);
    topk_kernel<<<BATCH, 32>>>(boxes, scores, labels, out);
    cudaMemsetAsync(out + FEAT_OFF, 0, (size_t)BATCH*TOPK*FCO*sizeof(float));
    sample_kernel<<<BATCH*TOPK, 256>>>(x);
    conv_kernel<<<FULL_BLOCKS + CROP_BLOCKS, 256, CONV_SMEM>>>(x, bc);
    fc_kernel<<<dim3(16, 21), 256>>>(Wf, bf, out);
}

// round 13
// speedup vs baseline: 1.9293x; 1.0330x over previous
#include <cuda_runtime.h>
#include <math.h>
#include <stdint.h>

typedef unsigned long long u64;

#define BATCH 8
#define NBOX  300
#define TOPK  20
#define HW    512
#define CROPS 64
#define OC    256
#define FCO   4096

// d_out layout (floats): Objects[8,20,4] | Object_features[8,20,4096] | valid[8,20] | fullframe[8,4096]
#define OBJ_OFF   0
#define FEAT_OFF  640
#define VALID_OFF 656000
#define FULL_OFF  656160

#define KSTEPS 19                      // 147 -> 152 (19 k-steps of 8)
#define NFRAG  (KSTEPS*8*32*4)         // 19456 floats per ct (weight fragments)
#define PLSTRIDE 544                   // plane stride (floats); phase stride 136 -> bank-clean
#define RAW_BYTES (22*PLSTRIDE*4)      // 21 data planes + 1 zero plane = 47872 B
#define DEC_OFF  RAW_BYTES             // int[152] k -> smem offset
#define CONV_SMEM (RAW_BYTES + 152*4)  // 48480 B
#define FULL_BLOCKS 2048
#define CROP_BLOCKS (BATCH*TOPK*4)     // job * 2 halves * 2 ct

__constant__ float c_mean[3] = {0.485f, 0.456f, 0.406f};
__constant__ float c_istd[3] = {1.0f/0.229f, 1.0f/0.224f, 1.0f/0.225f};

__device__ float g_pooled_full[BATCH*OC];
__device__ float g_pooled_crop[BATCH*TOPK*OC];
__device__ float g_crops[BATCH*TOPK*3*CROPS*CROPS];
__device__ __align__(16) float g_Wt[147*OC];         // [k][oc] for scalar crop conv
__device__ __align__(16) float g_WfragHi[2*NFRAG];   // rna-rounded tf32 weight fragments
__device__ float g_job_box[BATCH*TOPK*4];
__device__ int   g_job_b[BATCH*TOPK];
__device__ int   g_job_bk[BATCH*TOPK];
__device__ int   g_njobs;
__device__ int   g_lab64;

// ---------------------------------------------------------------- helpers
__device__ __forceinline__ void ffma2(u64 &d, u64 a, u64 b) {
    asm("fma.rn.f32x2 %0, %1, %2, %0;" : "+l"(d) : "l"(a), "l"(b));
}
__device__ __forceinline__ u64 dup2(float a) {
    u64 r; asm("mov.b64 %0, {%1, %1};" : "=l"(r) : "f"(a)); return r;
}
__device__ __forceinline__ void unpack2(u64 v, float &lo, float &hi) {
    asm("mov.b64 {%0, %1}, %2;" : "=f"(lo), "=f"(hi) : "l"(v));
}
__device__ __forceinline__ float tf32r(float a) {
    uint32_t u; asm("cvt.rna.tf32.f32 %0, %1;" : "=r"(u) : "f"(a));
    return __uint_as_float(u);
}
__device__ __forceinline__ void mma_tf32(float* d, const uint32_t* a, uint32_t b0, uint32_t b1) {
    asm volatile(
        "mma.sync.aligned.m16n8k8.row.col.f32.tf32.tf32.f32 "
        "{%0,%1,%2,%3}, {%4,%5,%6,%7}, {%8,%9}, {%0,%1,%2,%3};"
        : "+f"(d[0]), "+f"(d[1]), "+f"(d[2]), "+f"(d[3])
        : "r"(a[0]), "r"(a[1]), "r"(a[2]), "r"(a[3]), "r"(b0), "r"(b1));
}

// ---------------------------------------------------------------- prep
__global__ void prep_kernel(const float* __restrict__ Wc,
                            const long long* __restrict__ lab) {
    int gid = blockIdx.x*256 + threadIdx.x;
    if (gid < BATCH*OC)      g_pooled_full[gid] = 0.f;
    if (gid < BATCH*TOPK*OC) g_pooled_crop[gid] = 0.f;
    if (gid == 0)            g_njobs = 0;
    if (blockIdx.x < 147) {
        int k = blockIdx.x, c = threadIdx.x;
        g_Wt[k*OC + c] = Wc[c*147 + k];
    }
    // rna tf32 weight fragments: idx = (((ct*19+s)*8+Ml)*32+lane)*4+reg
    if (gid < 2*NFRAG) {
        int reg  = gid & 3;
        int lane = (gid >> 2) & 31;
        int Ml   = (gid >> 7) & 7;
        int ct   = gid / NFRAG;
        int s    = (gid - ct*NFRAG) >> 10;
        int oc = ct*128 + Ml*16 + (lane >> 2) + (reg & 1)*8;
        int k  = s*8 + (lane & 3) + (reg >> 1)*4;
        float wv = (k < 147) ? Wc[oc*147 + k] : 0.f;
        g_WfragHi[gid] = tf32r(wv);
    }
    if (blockIdx.x == 159) {
        // labels dtype probe: first 1200 int64 words == extent of an int32 buffer
        // of 2400 elems (never OOB). Real int64 labels all lie in [0,91).
        __shared__ int bad;
        if (threadIdx.x == 0) bad = 0;
        __syncthreads();
        for (int i = threadIdx.x; i < 1200; i += 256) {
            long long v = lab[i];
            if (v < 0 || v >= 91) bad = 1;
        }
        __syncthreads();
        if (threadIdx.x == 0) g_lab64 = bad ? 0 : 1;
    }
}

// ---------------------------------------------------------------- top-k: one warp per batch
__global__ void topk_kernel(const float* __restrict__ boxes,
                            const float* __restrict__ scores,
                            const void* __restrict__ labels_raw,
                            float* __restrict__ out) {
    int b = blockIdx.x;
    int t = threadIdx.x;
    int lab64 = g_lab64;
    const int*       l32 = (const int*)labels_raw;
    const long long* l64 = (const long long*)labels_raw;

    float v[10];
    #pragma unroll
    for (int r = 0; r < 10; r++) {
        int i = t + 32*r;
        float s = -INFINITY;
        if (i < NBOX) {
            long long l = lab64 ? l64[b*NBOX + i] : (long long)l32[b*NBOX + i];
            bool veh = (l==2)||(l==3)||(l==4)||(l==6)||(l==8);
            float sc = scores[b*NBOX + i];
            if (veh && sc > 0.8f) s = sc;
        }
        v[r] = s;
    }
    for (int k = 0; k < TOPK; k++) {
        float bv = -INFINITY; int bi = 0x7fffffff;
        #pragma unroll
        for (int r = 0; r < 10; r++) {
            int i = t + 32*r;
            if (v[r] > bv) { bv = v[r]; bi = i; }
        }
        #pragma unroll
        for (int o = 16; o > 0; o >>= 1) {
            float ov = __shfl_down_sync(0xffffffffu, bv, o);
            int   oi = __shfl_down_sync(0xffffffffu, bi, o);
            if (ov > bv || (ov == bv && oi < bi)) { bv = ov; bi = oi; }
        }
        bv = __shfl_sync(0xffffffffu, bv, 0);
        bi = __shfl_sync(0xffffffffu, bi, 0);
        bool valid = (bv != -INFINITY);
        if (valid && (bi & 31) == t) {
            int r = bi >> 5;
            #pragma unroll
            for (int rr = 0; rr < 10; rr++) if (rr == r) v[rr] = -INFINITY;
        }
        if (t == 0) {
            float b0=0.f,b1=0.f,b2=0.f,b3=0.f;
            if (valid) {
                const float* bp = boxes + (b*NBOX + bi)*4;
                b0=bp[0]; b1=bp[1]; b2=bp[2]; b3=bp[3];
            }
            int bk = b*TOPK + k;
            out[OBJ_OFF + bk*4+0] = b0;
            out[OBJ_OFF + bk*4+1] = b1;
            out[OBJ_OFF + bk*4+2] = b2;
            out[OBJ_OFF + bk*4+3] = b3;
            out[VALID_OFF + bk]   = valid ? 1.0f : 0.0f;
            if (valid && b2 > b0 && b3 > b1) {
                int pos = atomicAdd(&g_njobs, 1);
                g_job_box[pos*4+0]=b0; g_job_box[pos*4+1]=b1;
                g_job_box[pos*4+2]=b2; g_job_box[pos*4+3]=b3;
                g_job_b[pos]  = b;
                g_job_bk[pos] = bk;
            }
        }
    }
}

// ---------------------------------------------------------------- RoIAlign (normalized on the fly)
__global__ void sample_kernel(const float* __restrict__ x) {
    int j = blockIdx.x;
    if (j >= g_njobs) return;
    int b = g_job_b[j];
    float bx0 = g_job_box[j*4+0], by0 = g_job_box[j*4+1];
    float bx1 = g_job_box[j*4+2], by1 = g_job_box[j*4+3];
    for (int idx = threadIdx.x; idx < 3*CROPS*CROPS; idx += blockDim.x) {
        int c  = idx >> 12;
        int rem = idx & 4095;
        int yi = rem >> 6, xi = rem & 63;
        float ys = by0 + (yi + 0.5f)*(1.0f/CROPS)*(by1 - by0);
        float xs = bx0 + (xi + 0.5f)*(1.0f/CROPS)*(bx1 - bx0);
        float yf = floorf(ys), xf = floorf(xs);
        float wy = ys - yf,  wx = xs - xf;
        int y0 = min(max((int)yf, 0), HW-1); int y1 = min(y0+1, HW-1);
        int x0 = min(max((int)xf, 0), HW-1); int x1 = min(x0+1, HW-1);
        const float* img = x + ((long)b*3 + c)*HW*HW;
        float m = c_mean[c], is = c_istd[c];
        float Ia = (img[y0*HW + x0]-m)*is, Ib = (img[y0*HW + x1]-m)*is;
        float Ic = (img[y1*HW + x0]-m)*is, Id = (img[y1*HW + x1]-m)*is;
        g_crops[j*(3*CROPS*CROPS) + idx] =
            Ia*(1.f-wy)*(1.f-wx) + Ib*(1.f-wy)*wx + Ic*wy*(1.f-wx) + Id*wy*wx;
    }
}

// ---------------------------------------------------------------- unified conv
// bx < FULL_BLOCKS: tf32 mma fullframe tile (128 oc x 128 px).
//   Raw patch staged coalesced into smem (phase-decomposed, rna-rounded once),
//   B fragments assembled by direct stride-1 LDS in the mainloop.
// else: scalar FFMA2 crop tile (exact fp32).
__global__ void __launch_bounds__(256, 2) conv_kernel(const float* __restrict__ x,
                                                      const float* __restrict__ bc) {
    extern __shared__ char smc[];
    int t = threadIdx.x;
    int w = t >> 5, lane = t & 31;
    int bx = blockIdx.x;

    if (bx < FULL_BLOCKS) {
        float* smP = (float*)smc;
        int*   dec = (int*)(smc + DEC_OFF);
        int ocg = w & 3, pxg = w >> 2;
        int ct = bx & 1, tile = bx >> 1;
        int oy = tile & 127, b = tile >> 7;
        int c0 = ct*128;

        // decode table: k -> smem offset of v(k, px=0)
        if (t < 152) {
            int k = t, v;
            if (k < 147) {
                int cin = k/49; int rr = k - cin*49;
                int ky = rr/7;  int kx = rr - ky*7;
                v = (cin*7 + ky)*PLSTRIDE + (kx&3)*136 + (kx>>2);
            } else v = 21*PLSTRIDE;     // zero plane
            dec[k] = v;
        }
        // stage raw patch: 21 planes, coalesced rows, normalized + rna-rounded once
        {
            int iyb = 4*oy - 1;
            #pragma unroll 1
            for (int plane = 0; plane < 21; plane++) {
                int cin = plane/7, ky = plane - cin*7;
                int iy = iyb + ky;
                const float* xr = x + (((long)b*3 + cin)*512 + iy)*512;
                float m = c_mean[cin], is = c_istd[cin];
                float* sp = smP + plane*PLSTRIDE;
                bool rowok = (unsigned)iy < 512u;
                #pragma unroll
                for (int p0 = 0; p0 < 516; p0 += 256) {
                    int p = p0 + t;
                    if (p < 516) {
                        int ix = p - 1;
                        float v = 0.f;
                        if (rowok && (unsigned)ix < 512u) v = tf32r((xr[ix] - m)*is);
                        sp[(p&3)*136 + (p>>2)] = v;
                    }
                }
            }
            // zero plane 21 (padding for k >= 147)
            for (int p = t; p < PLSTRIDE; p += 256) smP[21*PLSTRIDE + p] = 0.f;
        }
        __syncthreads();

        float d[2][8][4];
        #pragma unroll
        for (int mt = 0; mt < 2; mt++)
            #pragma unroll
            for (int nt = 0; nt < 8; nt++)
                #pragma unroll
                for (int r = 0; r < 4; r++) d[mt][nt][r] = 0.f;

        const uint4* aH = (const uint4*)g_WfragHi + ((ct*KSTEPS)*8 + ocg*2)*32 + lane;
        int k0  = lane & 3;
        int pxb = pxg*64 + (lane >> 2);
        uint4 nh0 = aH[0], nh1 = aH[32];
        #pragma unroll 1
        for (int s = 0; s < KSTEPS; s++) {
            uint4 h0 = nh0, h1 = nh1;
            int sn = (s + 1 < KSTEPS) ? s + 1 : s;
            nh0 = aH[(sn*8)*32];  nh1 = aH[(sn*8 + 1)*32];
            int ka = s*8 + k0;
            const float* pa = smP + dec[ka]     + pxb;
            const float* pb = smP + dec[ka + 4] + pxb;
            uint32_t bA[8], bB[8];
            #pragma unroll
            for (int j = 0; j < 8; j++) {
                bA[j] = __float_as_uint(pa[j*8]);
                bB[j] = __float_as_uint(pb[j*8]);
            }
            const uint32_t* ph0 = (const uint32_t*)&h0;
            const uint32_t* ph1 = (const uint32_t*)&h1;
            mma_tf32(d[0][0], ph0, bA[0], bB[0]);
            mma_tf32(d[0][1], ph0, bA[1], bB[1]);
            mma_tf32(d[0][2], ph0, bA[2], bB[2]);
            mma_tf32(d[0][3], ph0, bA[3], bB[3]);
            mma_tf32(d[0][4], ph0, bA[4], bB[4]);
            mma_tf32(d[0][5], ph0, bA[5], bB[5]);
            mma_tf32(d[0][6], ph0, bA[6], bB[6]);
            mma_tf32(d[0][7], ph0, bA[7], bB[7]);
            mma_tf32(d[1][0], ph1, bA[0], bB[0]);
            mma_tf32(d[1][1], ph1, bA[1], bB[1]);
            mma_tf32(d[1][2], ph1, bA[2], bB[2]);
            mma_tf32(d[1][3], ph1, bA[3], bB[3]);
            mma_tf32(d[1][4], ph1, bA[4], bB[4]);
            mma_tf32(d[1][5], ph1, bA[5], bB[5]);
            mma_tf32(d[1][6], ph1, bA[6], bB[6]);
            mma_tf32(d[1][7], ph1, bA[7], bB[7]);
        }

        // epilogue: bias + relu + pool over px, atomic accumulate
        #pragma unroll
        for (int mt = 0; mt < 2; mt++) {
            int oc_r0 = c0 + ocg*32 + mt*16 + (lane >> 2);
            float bias0 = bc[oc_r0];
            float bias1 = bc[oc_r0 + 8];
            float s0 = 0.f, s1 = 0.f;
            #pragma unroll
            for (int nt = 0; nt < 8; nt++) {
                s0 += fmaxf(d[mt][nt][0] + bias0, 0.f) + fmaxf(d[mt][nt][1] + bias0, 0.f);
                s1 += fmaxf(d[mt][nt][2] + bias1, 0.f) + fmaxf(d[mt][nt][3] + bias1, 0.f);
            }
            s0 += __shfl_xor_sync(0xffffffffu, s0, 1);
            s0 += __shfl_xor_sync(0xffffffffu, s0, 2);
            s1 += __shfl_xor_sync(0xffffffffu, s1, 1);
            s1 += __shfl_xor_sync(0xffffffffu, s1, 2);
            if ((lane & 3) == 0) {
                atomicAdd(&g_pooled_full[b*OC + oc_r0],     s0);
                atomicAdd(&g_pooled_full[b*OC + oc_r0 + 8], s1);
            }
        }
    } else {
        // ------------- crop: half (8 out-rows = 128 px) x 128 channels, exact fp32
        float* sm = (float*)smc;
        int pxg = lane, cg = w;
        int cx2 = bx - FULL_BLOCKS;
        int ct = cx2 & 1; int half = (cx2 >> 1) & 1; int j = cx2 >> 2;
        if (j >= g_njobs) return;
        int c0 = ct*128;
        const float* crop = g_crops + (long)j*(3*CROPS*CROPS);
        int iy0 = half*32 - 1;
        for (int s = t; s < 105*67; s += 256) {
            int row = s / 67; int p = s - row*67;
            int cin = row / 35; int iyl = row - cin*35;
            int cy = iy0 + iyl, cxx = p - 1;
            float v = 0.f;
            if ((unsigned)cy < 64u && (unsigned)cxx < 64u)
                v = crop[(cin*64 + cy)*64 + cxx];
            sm[row*84 + (p&3)*18 + (p>>2)] = v;
        }
        __syncthreads();

        int rowoff[4];
        #pragma unroll
        for (int m = 0; m < 4; m++) {
            int px = pxg + 32*m;
            rowoff[m] = (px >> 4)*4*84 + (px & 15);
        }
        u64 acc[4][8];
        {
            const u64* b2 = (const u64*)(bc + c0 + cg*16);
            #pragma unroll
            for (int i = 0; i < 8; i++) {
                u64 bb = b2[i];
                acc[0][i]=bb; acc[1][i]=bb; acc[2][i]=bb; acc[3][i]=bb;
            }
        }
        const float* wbase = g_Wt + c0 + cg*16;
        for (int cin = 0; cin < 3; cin++) {
            const float* plc = sm + cin*35*84;
            const float* wc  = wbase + cin*49*OC;
            #pragma unroll
            for (int ky = 0; ky < 7; ky++) {
                #pragma unroll
                for (int kx = 0; kx < 7; kx++) {
                    const float* pl = plc + ky*84 + (kx&3)*18 + (kx>>2);
                    float a0 = pl[rowoff[0]], a1 = pl[rowoff[1]];
                    float a2 = pl[rowoff[2]], a3 = pl[rowoff[3]];
                    const ulonglong2* wp = (const ulonglong2*)(wc + (ky*7+kx)*OC);
                    ulonglong2 wA = wp[0], wB = wp[1], wC = wp[2], wD = wp[3];
                    u64 dd;
                    dd = dup2(a0);
                    ffma2(acc[0][0],dd,wA.x); ffma2(acc[0][1],dd,wA.y); ffma2(acc[0][2],dd,wB.x); ffma2(acc[0][3],dd,wB.y);
                    ffma2(acc[0][4],dd,wC.x); ffma2(acc[0][5],dd,wC.y); ffma2(acc[0][6],dd,wD.x); ffma2(acc[0][7],dd,wD.y);
                    dd = dup2(a1);
                    ffma2(acc[1][0],dd,wA.x); ffma2(acc[1][1],dd,wA.y); ffma2(acc[1][2],dd,wB.x); ffma2(acc[1][3],dd,wB.y);
                    ffma2(acc[1][4],dd,wC.x); ffma2(acc[1][5],dd,wC.y); ffma2(acc[1][6],dd,wD.x); ffma2(acc[1][7],dd,wD.y);
                    dd = dup2(a2);
                    ffma2(acc[2][0],dd,wA.x); ffma2(acc[2][1],dd,wA.y); ffma2(acc[2][2],dd,wB.x); ffma2(acc[2][3],dd,wB.y);
                    ffma2(acc[2][4],dd,wC.x); ffma2(acc[2][5],dd,wC.y); ffma2(acc[2][6],dd,wD.x); ffma2(acc[2][7],dd,wD.y);
                    dd = dup2(a3);
                    ffma2(acc[3][0],dd,wA.x); ffma2(acc[3][1],dd,wA.y); ffma2(acc[3][2],dd,wB.x); ffma2(acc[3][3],dd,wB.y);
                    ffma2(acc[3][4],dd,wC.x); ffma2(acc[3][5],dd,wC.y); ffma2(acc[3][6],dd,wD.x); ffma2(acc[3][7],dd,wD.y);
                }
            }
        }
        #pragma unroll
        for (int i = 0; i < 8; i++) {
            float s0 = 0.f, s1 = 0.f;
            #pragma unroll
            for (int m = 0; m < 4; m++) {
                float lo, hi; unpack2(acc[m][i], lo, hi);
                s0 += fmaxf(lo, 0.f); s1 += fmaxf(hi, 0.f);
            }
            #pragma unroll
            for (int o = 16; o > 0; o >>= 1) {
                s0 += __shfl_down_sync(0xffffffffu, s0, o);
                s1 += __shfl_down_sync(0xffffffffu, s1, o);
            }
            if (pxg == 0) {
                atomicAdd(&g_pooled_crop[j*OC + c0 + cg*16 + 2*i],     s0);
                atomicAdd(&g_pooled_crop[j*OC + c0 + cg*16 + 2*i + 1], s1);
            }
        }
    }
}

// ---------------------------------------------------------------- unified FC
__global__ void __launch_bounds__(256) fc_kernel(const float* __restrict__ Wf,
                                                 const float* __restrict__ bf,
                                                 float* __restrict__ out) {
    int y = blockIdx.y, t = threadIdx.x;
    int o = blockIdx.x*256 + t;
    __shared__ float sp[8*OC];
    if (y == 0) {
        for (int s = t; s < BATCH*OC; s += 256)
            sp[s] = g_pooled_full[s] * (1.0f/16384.0f);
        __syncthreads();
        float acc[8] = {0.f,0.f,0.f,0.f,0.f,0.f,0.f,0.f};
        for (int c = 0; c < OC; c++) {
            float w = Wf[(long)c*FCO + o];
            #pragma unroll
            for (int b2 = 0; b2 < 8; b2++) acc[b2] += sp[b2*OC + c] * w;
        }
        float bias = bf[o];
        #pragma unroll
        for (int b2 = 0; b2 < 8; b2++)
            out[FULL_OFF + b2*FCO + o] = acc[b2] + bias;
    } else {
        int nj = g_njobs;
        int j0 = (y - 1)*8;
        if (j0 >= nj) return;
        for (int s = t; s < 8*OC; s += 256) {
            int jj = s >> 8; int c = s & 255;
            int j = j0 + jj;
            sp[s] = (j < nj) ? g_pooled_crop[j*OC + c] * (1.0f/256.0f) : 0.f;
        }
        __syncthreads();
        float acc[8] = {0.f,0.f,0.f,0.f,0.f,0.f,0.f,0.f};
        for (int c = 0; c < OC; c++) {
            float w = Wf[(long)c*FCO + o];
            #pragma unroll
            for (int jj = 0; jj < 8; jj++) acc[jj] += sp[jj*OC + c] * w;
        }
        float bias = bf[o];
        #pragma unroll
        for (int jj = 0; jj < 8; jj++) {
            int j = j0 + jj;
            if (j < nj)
                out[FEAT_OFF + (long)g_job_bk[j]*FCO + o] = acc[jj] + bias;
        }
    }
}

// ---------------------------------------------------------------- launch
extern "C" void kernel_launch(void* const* d_in, const int* in_sizes, int n_in,
                              void* d_out, int out_size) {
    const float* x      = (const float*)d_in[0];
    const float* boxes  = (const float*)d_in[1];
    const float* scores = (const float*)d_in[2];
    const void*  labels = d_in[3];
    const float* Wc     = (const float*)d_in[4];
    const float* bc     = (const float*)d_in[5];
    const float* Wf     = (const float*)d_in[6];
    const float* bf     = (const float*)d_in[7];
    float* out = (float*)d_out;

    cudaFuncSetAttribute(conv_kernel, cudaFuncAttributeMaxDynamicSharedMemorySize, CONV_SMEM);

    prep_kernel<<<320, 256>>>(Wc, (const long long*)labels);
    topk_kernel<<<BATCH, 32>>>(boxes, scores, labels, out);
    cudaMemsetAsync(out + FEAT_OFF, 0, (size_t)BATCH*TOPK*FCO*sizeof(float));
    sample_kernel<<<BATCH*TOPK, 256>>>(x);
    conv_kernel<<<FULL_BLOCKS + CROP_BLOCKS, 256, CONV_SMEM>>>(x, bc);
    fc_kernel<<<dim3(16, 21), 256>>>(Wf, bf, out);
}

// round 14
// speedup vs baseline: 1.9456x; 1.0084x over previous
#include <cuda_runtime.h>
#include <math.h>
#include <stdint.h>

typedef unsigned long long u64;

#define BATCH 8
#define NBOX  300
#define TOPK  20
#define HW    512
#define CROPS 64
#define OC    256
#define FCO   4096

// d_out layout (floats): Objects[8,20,4] | Object_features[8,20,4096] | valid[8,20] | fullframe[8,4096]
#define OBJ_OFF   0
#define FEAT_OFF  640
#define VALID_OFF 656000
#define FULL_OFF  656160

#define KSTEPS 19                      // 147 -> 152 (19 k-steps of 8)
#define NFRAG  (KSTEPS*8*32*4)         // 19456 floats per ct (weight fragments)
#define PLSTRIDE 544                   // plane stride (floats); phase stride 136 -> bank-clean
#define RAW_BYTES (22*PLSTRIDE*4)      // 21 data planes + 1 zero plane = 47872 B
#define DEC_OFF  RAW_BYTES             // int[152] k -> smem offset
#define CONV_SMEM (RAW_BYTES + 152*4)  // 48480 B
#define FULL_BLOCKS 1024               // one block per (oy, b): 256 oc x 128 px
#define CROP_BLOCKS (BATCH*TOPK*4)     // job * 2 halves * 2 ct

__constant__ float c_mean[3] = {0.485f, 0.456f, 0.406f};
__constant__ float c_istd[3] = {1.0f/0.229f, 1.0f/0.224f, 1.0f/0.225f};

__device__ float g_pooled_full[BATCH*OC];
__device__ float g_pooled_crop[BATCH*TOPK*OC];
__device__ float g_crops[BATCH*TOPK*3*CROPS*CROPS];
__device__ __align__(16) float g_Wt[147*OC];         // [k][oc] for scalar crop conv
__device__ __align__(16) float g_WfragHi[2*NFRAG];   // rna-rounded tf32 weight fragments
__device__ float g_job_box[BATCH*TOPK*4];
__device__ int   g_job_b[BATCH*TOPK];
__device__ int   g_job_bk[BATCH*TOPK];
__device__ int   g_njobs;
__device__ int   g_lab64;

// ---------------------------------------------------------------- helpers
__device__ __forceinline__ void ffma2(u64 &d, u64 a, u64 b) {
    asm("fma.rn.f32x2 %0, %1, %2, %0;" : "+l"(d) : "l"(a), "l"(b));
}
__device__ __forceinline__ u64 dup2(float a) {
    u64 r; asm("mov.b64 %0, {%1, %1};" : "=l"(r) : "f"(a)); return r;
}
__device__ __forceinline__ void unpack2(u64 v, float &lo, float &hi) {
    asm("mov.b64 {%0, %1}, %2;" : "=f"(lo), "=f"(hi) : "l"(v));
}
__device__ __forceinline__ float tf32r(float a) {
    uint32_t u; asm("cvt.rna.tf32.f32 %0, %1;" : "=r"(u) : "f"(a));
    return __uint_as_float(u);
}
__device__ __forceinline__ void mma_tf32(float* d, const uint32_t* a, uint32_t b0, uint32_t b1) {
    asm volatile(
        "mma.sync.aligned.m16n8k8.row.col.f32.tf32.tf32.f32 "
        "{%0,%1,%2,%3}, {%4,%5,%6,%7}, {%8,%9}, {%0,%1,%2,%3};"
        : "+f"(d[0]), "+f"(d[1]), "+f"(d[2]), "+f"(d[3])
        : "r"(a[0]), "r"(a[1]), "r"(a[2]), "r"(a[3]), "r"(b0), "r"(b1));
}

// ---------------------------------------------------------------- prep
__global__ void prep_kernel(const float* __restrict__ Wc,
                            const long long* __restrict__ lab) {
    int gid = blockIdx.x*256 + threadIdx.x;
    if (gid < BATCH*OC)      g_pooled_full[gid] = 0.f;
    if (gid < BATCH*TOPK*OC) g_pooled_crop[gid] = 0.f;
    if (gid == 0)            g_njobs = 0;
    if (blockIdx.x < 147) {
        int k = blockIdx.x, c = threadIdx.x;
        g_Wt[k*OC + c] = Wc[c*147 + k];
    }
    // rna tf32 weight fragments: idx = (((ct*19+s)*8+Ml)*32+lane)*4+reg
    if (gid < 2*NFRAG) {
        int reg  = gid & 3;
        int lane = (gid >> 2) & 31;
        int Ml   = (gid >> 7) & 7;
        int ct   = gid / NFRAG;
        int s    = (gid - ct*NFRAG) >> 10;
        int oc = ct*128 + Ml*16 + (lane >> 2) + (reg & 1)*8;
        int k  = s*8 + (lane & 3) + (reg >> 1)*4;
        float wv = (k < 147) ? Wc[oc*147 + k] : 0.f;
        g_WfragHi[gid] = tf32r(wv);
    }
    if (blockIdx.x == 159) {
        // labels dtype probe: first 1200 int64 words == extent of an int32 buffer
        // of 2400 elems (never OOB). Real int64 labels all lie in [0,91).
        __shared__ int bad;
        if (threadIdx.x == 0) bad = 0;
        __syncthreads();
        for (int i = threadIdx.x; i < 1200; i += 256) {
            long long v = lab[i];
            if (v < 0 || v >= 91) bad = 1;
        }
        __syncthreads();
        if (threadIdx.x == 0) g_lab64 = bad ? 0 : 1;
    }
}

// ---------------------------------------------------------------- top-k: one warp per batch
__global__ void topk_kernel(const float* __restrict__ boxes,
                            const float* __restrict__ scores,
                            const void* __restrict__ labels_raw,
                            float* __restrict__ out) {
    int b = blockIdx.x;
    int t = threadIdx.x;
    int lab64 = g_lab64;
    const int*       l32 = (const int*)labels_raw;
    const long long* l64 = (const long long*)labels_raw;

    float v[10];
    #pragma unroll
    for (int r = 0; r < 10; r++) {
        int i = t + 32*r;
        float s = -INFINITY;
        if (i < NBOX) {
            long long l = lab64 ? l64[b*NBOX + i] : (long long)l32[b*NBOX + i];
            bool veh = (l==2)||(l==3)||(l==4)||(l==6)||(l==8);
            float sc = scores[b*NBOX + i];
            if (veh && sc > 0.8f) s = sc;
        }
        v[r] = s;
    }
    for (int k = 0; k < TOPK; k++) {
        float bv = -INFINITY; int bi = 0x7fffffff;
        #pragma unroll
        for (int r = 0; r < 10; r++) {
            int i = t + 32*r;
            if (v[r] > bv) { bv = v[r]; bi = i; }
        }
        #pragma unroll
        for (int o = 16; o > 0; o >>= 1) {
            float ov = __shfl_down_sync(0xffffffffu, bv, o);
            int   oi = __shfl_down_sync(0xffffffffu, bi, o);
            if (ov > bv || (ov == bv && oi < bi)) { bv = ov; bi = oi; }
        }
        bv = __shfl_sync(0xffffffffu, bv, 0);
        bi = __shfl_sync(0xffffffffu, bi, 0);
        bool valid = (bv != -INFINITY);
        if (valid && (bi & 31) == t) {
            int r = bi >> 5;
            #pragma unroll
            for (int rr = 0; rr < 10; rr++) if (rr == r) v[rr] = -INFINITY;
        }
        if (t == 0) {
            float b0=0.f,b1=0.f,b2=0.f,b3=0.f;
            if (valid) {
                const float* bp = boxes + (b*NBOX + bi)*4;
                b0=bp[0]; b1=bp[1]; b2=bp[2]; b3=bp[3];
            }
            int bk = b*TOPK + k;
            out[OBJ_OFF + bk*4+0] = b0;
            out[OBJ_OFF + bk*4+1] = b1;
            out[OBJ_OFF + bk*4+2] = b2;
            out[OBJ_OFF + bk*4+3] = b3;
            out[VALID_OFF + bk]   = valid ? 1.0f : 0.0f;
            if (valid && b2 > b0 && b3 > b1) {
                int pos = atomicAdd(&g_njobs, 1);
                g_job_box[pos*4+0]=b0; g_job_box[pos*4+1]=b1;
                g_job_box[pos*4+2]=b2; g_job_box[pos*4+3]=b3;
                g_job_b[pos]  = b;
                g_job_bk[pos] = bk;
            }
        }
    }
}

// ---------------------------------------------------------------- RoIAlign (normalized on the fly)
__global__ void sample_kernel(const float* __restrict__ x) {
    int j = blockIdx.x;
    if (j >= g_njobs) return;
    int b = g_job_b[j];
    float bx0 = g_job_box[j*4+0], by0 = g_job_box[j*4+1];
    float bx1 = g_job_box[j*4+2], by1 = g_job_box[j*4+3];
    for (int idx = threadIdx.x; idx < 3*CROPS*CROPS; idx += blockDim.x) {
        int c  = idx >> 12;
        int rem = idx & 4095;
        int yi = rem >> 6, xi = rem & 63;
        float ys = by0 + (yi + 0.5f)*(1.0f/CROPS)*(by1 - by0);
        float xs = bx0 + (xi + 0.5f)*(1.0f/CROPS)*(bx1 - bx0);
        float yf = floorf(ys), xf = floorf(xs);
        float wy = ys - yf,  wx = xs - xf;
        int y0 = min(max((int)yf, 0), HW-1); int y1 = min(y0+1, HW-1);
        int x0 = min(max((int)xf, 0), HW-1); int x1 = min(x0+1, HW-1);
        const float* img = x + ((long)b*3 + c)*HW*HW;
        float m = c_mean[c], is = c_istd[c];
        float Ia = (img[y0*HW + x0]-m)*is, Ib = (img[y0*HW + x1]-m)*is;
        float Ic = (img[y1*HW + x0]-m)*is, Id = (img[y1*HW + x1]-m)*is;
        g_crops[j*(3*CROPS*CROPS) + idx] =
            Ia*(1.f-wy)*(1.f-wx) + Ib*(1.f-wy)*wx + Ic*wy*(1.f-wx) + Id*wy*wx;
    }
}

// ---------------------------------------------------------------- unified conv (512 threads)
// bx < FULL_BLOCKS: tf32 mma fullframe tile (256 oc x 128 px), patch staged ONCE.
//   16 warps: ocg = w&7 (32 oc, ct = ocg>>2), pxg = w>>3 (64 px).
// else: scalar FFMA2 crop tile (exact fp32, warps 0-7 compute).
__global__ void __launch_bounds__(512, 1) conv_kernel(const float* __restrict__ x,
                                                      const float* __restrict__ bc) {
    extern __shared__ char smc[];
    int t = threadIdx.x;
    int w = t >> 5, lane = t & 31;
    int bx = blockIdx.x;

    if (bx < FULL_BLOCKS) {
        float* smP = (float*)smc;
        int*   dec = (int*)(smc + DEC_OFF);
        int ocg = w & 7, pxg = w >> 3;
        int ct  = ocg >> 2;
        int oy = bx & 127, b = bx >> 7;
        int c0 = ct*128;

        // decode table: k -> smem offset of v(k, px=0)
        if (t < 152) {
            int k = t, v;
            if (k < 147) {
                int cin = k/49; int rr = k - cin*49;
                int ky = rr/7;  int kx = rr - ky*7;
                v = (cin*7 + ky)*PLSTRIDE + (kx&3)*136 + (kx>>2);
            } else v = 21*PLSTRIDE;     // zero plane
            dec[k] = v;
        }
        // stage raw patch: 21 planes, coalesced, normalized + rna-rounded once
        {
            int iyb = 4*oy - 1;
            #pragma unroll 3
            for (int plane = 0; plane < 21; plane++) {
                int cin = plane/7, ky = plane - cin*7;
                int iy = iyb + ky;
                const float* xr = x + (((long)b*3 + cin)*512 + iy)*512;
                float m = c_mean[cin], is = c_istd[cin];
                float* sp = smP + plane*PLSTRIDE;
                bool rowok = (unsigned)iy < 512u;
                {
                    int p = t;                    // 0..511
                    int ix = p - 1;
                    float v = 0.f;
                    if (rowok && (unsigned)ix < 512u) v = tf32r((xr[ix] - m)*is);
                    sp[(p&3)*136 + (p>>2)] = v;
                }
                if (t < 4) {
                    int p = 512 + t;              // 512..515
                    int ix = p - 1;
                    float v = 0.f;
                    if (rowok && (unsigned)ix < 512u) v = tf32r((xr[ix] - m)*is);
                    sp[(p&3)*136 + (p>>2)] = v;
                }
            }
            for (int p = t; p < PLSTRIDE; p += 512) smP[21*PLSTRIDE + p] = 0.f;
        }
        __syncthreads();

        float d[2][8][4];
        #pragma unroll
        for (int mt = 0; mt < 2; mt++)
            #pragma unroll
            for (int nt = 0; nt < 8; nt++)
                #pragma unroll
                for (int r = 0; r < 4; r++) d[mt][nt][r] = 0.f;

        const uint4* aH = (const uint4*)g_WfragHi
                        + ((ct*KSTEPS)*8 + (ocg & 3)*2)*32 + lane;
        int k0  = lane & 3;
        int pxb = pxg*64 + (lane >> 2);
        uint4 nh0 = aH[0], nh1 = aH[32];
        #pragma unroll 1
        for (int s = 0; s < KSTEPS; s++) {
            uint4 h0 = nh0, h1 = nh1;
            int sn = (s + 1 < KSTEPS) ? s + 1 : s;
            nh0 = aH[(sn*8)*32];  nh1 = aH[(sn*8 + 1)*32];
            int ka = s*8 + k0;
            const float* pa = smP + dec[ka]     + pxb;
            const float* pb = smP + dec[ka + 4] + pxb;
            uint32_t bA[8], bB[8];
            #pragma unroll
            for (int j = 0; j < 8; j++) {
                bA[j] = __float_as_uint(pa[j*8]);
                bB[j] = __float_as_uint(pb[j*8]);
            }
            const uint32_t* ph0 = (const uint32_t*)&h0;
            const uint32_t* ph1 = (const uint32_t*)&h1;
            mma_tf32(d[0][0], ph0, bA[0], bB[0]);
            mma_tf32(d[0][1], ph0, bA[1], bB[1]);
            mma_tf32(d[0][2], ph0, bA[2], bB[2]);
            mma_tf32(d[0][3], ph0, bA[3], bB[3]);
            mma_tf32(d[0][4], ph0, bA[4], bB[4]);
            mma_tf32(d[0][5], ph0, bA[5], bB[5]);
            mma_tf32(d[0][6], ph0, bA[6], bB[6]);
            mma_tf32(d[0][7], ph0, bA[7], bB[7]);
            mma_tf32(d[1][0], ph1, bA[0], bB[0]);
            mma_tf32(d[1][1], ph1, bA[1], bB[1]);
            mma_tf32(d[1][2], ph1, bA[2], bB[2]);
            mma_tf32(d[1][3], ph1, bA[3], bB[3]);
            mma_tf32(d[1][4], ph1, bA[4], bB[4]);
            mma_tf32(d[1][5], ph1, bA[5], bB[5]);
            mma_tf32(d[1][6], ph1, bA[6], bB[6]);
            mma_tf32(d[1][7], ph1, bA[7], bB[7]);
        }

        // epilogue: bias + relu + pool over px, atomic accumulate
        #pragma unroll
        for (int mt = 0; mt < 2; mt++) {
            int oc_r0 = c0 + (ocg & 3)*32 + mt*16 + (lane >> 2);
            float bias0 = bc[oc_r0];
            float bias1 = bc[oc_r0 + 8];
            float s0 = 0.f, s1 = 0.f;
            #pragma unroll
            for (int nt = 0; nt < 8; nt++) {
                s0 += fmaxf(d[mt][nt][0] + bias0, 0.f) + fmaxf(d[mt][nt][1] + bias0, 0.f);
                s1 += fmaxf(d[mt][nt][2] + bias1, 0.f) + fmaxf(d[mt][nt][3] + bias1, 0.f);
            }
            s0 += __shfl_xor_sync(0xffffffffu, s0, 1);
            s0 += __shfl_xor_sync(0xffffffffu, s0, 2);
            s1 += __shfl_xor_sync(0xffffffffu, s1, 1);
            s1 += __shfl_xor_sync(0xffffffffu, s1, 2);
            if ((lane & 3) == 0) {
                atomicAdd(&g_pooled_full[b*OC + oc_r0],     s0);
                atomicAdd(&g_pooled_full[b*OC + oc_r0 + 8], s1);
            }
        }
    } else {
        // ------------- crop: half (8 out-rows = 128 px) x 128 channels, exact fp32
        float* sm = (float*)smc;
        int cx2 = bx - FULL_BLOCKS;
        int ct = cx2 & 1; int half = (cx2 >> 1) & 1; int j = cx2 >> 2;
        if (j >= g_njobs) return;
        int c0 = ct*128;
        const float* crop = g_crops + (long)j*(3*CROPS*CROPS);
        int iy0 = half*32 - 1;
        for (int s = t; s < 105*67; s += 512) {
            int row = s / 67; int p = s - row*67;
            int cin = row / 35; int iyl = row - cin*35;
            int cy = iy0 + iyl, cxx = p - 1;
            float v = 0.f;
            if ((unsigned)cy < 64u && (unsigned)cxx < 64u)
                v = crop[(cin*64 + cy)*64 + cxx];
            sm[row*84 + (p&3)*18 + (p>>2)] = v;
        }
        __syncthreads();
        if (w >= 8) return;             // warps 8-15 only helped stage
        int pxg = lane, cg = w;

        int rowoff[4];
        #pragma unroll
        for (int m = 0; m < 4; m++) {
            int px = pxg + 32*m;
            rowoff[m] = (px >> 4)*4*84 + (px & 15);
        }
        u64 acc[4][8];
        {
            const u64* b2 = (const u64*)(bc + c0 + cg*16);
            #pragma unroll
            for (int i = 0; i < 8; i++) {
                u64 bb = b2[i];
                acc[0][i]=bb; acc[1][i]=bb; acc[2][i]=bb; acc[3][i]=bb;
            }
        }
        const float* wbase = g_Wt + c0 + cg*16;
        for (int cin = 0; cin < 3; cin++) {
            const float* plc = sm + cin*35*84;
            const float* wc  = wbase + cin*49*OC;
            #pragma unroll
            for (int ky = 0; ky < 7; ky++) {
                #pragma unroll
                for (int kx = 0; kx < 7; kx++) {
                    const float* pl = plc + ky*84 + (kx&3)*18 + (kx>>2);
                    float a0 = pl[rowoff[0]], a1 = pl[rowoff[1]];
                    float a2 = pl[rowoff[2]], a3 = pl[rowoff[3]];
                    const ulonglong2* wp = (const ulonglong2*)(wc + (ky*7+kx)*OC);
                    ulonglong2 wA = wp[0], wB = wp[1], wC = wp[2], wD = wp[3];
                    u64 dd;
                    dd = dup2(a0);
                    ffma2(acc[0][0],dd,wA.x); ffma2(acc[0][1],dd,wA.y); ffma2(acc[0][2],dd,wB.x); ffma2(acc[0][3],dd,wB.y);
                    ffma2(acc[0][4],dd,wC.x); ffma2(acc[0][5],dd,wC.y); ffma2(acc[0][6],dd,wD.x); ffma2(acc[0][7],dd,wD.y);
                    dd = dup2(a1);
                    ffma2(acc[1][0],dd,wA.x); ffma2(acc[1][1],dd,wA.y); ffma2(acc[1][2],dd,wB.x); ffma2(acc[1][3],dd,wB.y);
                    ffma2(acc[1][4],dd,wC.x); ffma2(acc[1][5],dd,wC.y); ffma2(acc[1][6],dd,wD.x); ffma2(acc[1][7],dd,wD.y);
                    dd = dup2(a2);
                    ffma2(acc[2][0],dd,wA.x); ffma2(acc[2][1],dd,wA.y); ffma2(acc[2][2],dd,wB.x); ffma2(acc[2][3],dd,wB.y);
                    ffma2(acc[2][4],dd,wC.x); ffma2(acc[2][5],dd,wC.y); ffma2(acc[2][6],dd,wD.x); ffma2(acc[2][7],dd,wD.y);
                    dd = dup2(a3);
                    ffma2(acc[3][0],dd,wA.x); ffma2(acc[3][1],dd,wA.y); ffma2(acc[3][2],dd,wB.x); ffma2(acc[3][3],dd,wB.y);
                    ffma2(acc[3][4],dd,wC.x); ffma2(acc[3][5],dd,wC.y); ffma2(acc[3][6],dd,wD.x); ffma2(acc[3][7],dd,wD.y);
                }
            }
        }
        #pragma unroll
        for (int i = 0; i < 8; i++) {
            float s0 = 0.f, s1 = 0.f;
            #pragma unroll
            for (int m = 0; m < 4; m++) {
                float lo, hi; unpack2(acc[m][i], lo, hi);
                s0 += fmaxf(lo, 0.f); s1 += fmaxf(hi, 0.f);
            }
            #pragma unroll
            for (int o = 16; o > 0; o >>= 1) {
                s0 += __shfl_down_sync(0xffffffffu, s0, o);
                s1 += __shfl_down_sync(0xffffffffu, s1, o);
            }
            if (pxg == 0) {
                atomicAdd(&g_pooled_crop[j*OC + c0 + cg*16 + 2*i],     s0);
                atomicAdd(&g_pooled_crop[j*OC + c0 + cg*16 + 2*i + 1], s1);
            }
        }
    }
}

// ---------------------------------------------------------------- unified FC
__global__ void __launch_bounds__(256) fc_kernel(const float* __restrict__ Wf,
                                                 const float* __restrict__ bf,
                                                 float* __restrict__ out) {
    int y = blockIdx.y, t = threadIdx.x;
    int o = blockIdx.x*256 + t;
    __shared__ float sp[8*OC];
    if (y == 0) {
        for (int s = t; s < BATCH*OC; s += 256)
            sp[s] = g_pooled_full[s] * (1.0f/16384.0f);
        __syncthreads();
        float acc[8] = {0.f,0.f,0.f,0.f,0.f,0.f,0.f,0.f};
        for (int c = 0; c < OC; c++) {
            float w = Wf[(long)c*FCO + o];
            #pragma unroll
            for (int b2 = 0; b2 < 8; b2++) acc[b2] += sp[b2*OC + c] * w;
        }
        float bias = bf[o];
        #pragma unroll
        for (int b2 = 0; b2 < 8; b2++)
            out[FULL_OFF + b2*FCO + o] = acc[b2] + bias;
    } else {
        int nj = g_njobs;
        int j0 = (y - 1)*8;
        if (j0 >= nj) return;
        for (int s = t; s < 8*OC; s += 256) {
            int jj = s >> 8; int c = s & 255;
            int j = j0 + jj;
            sp[s] = (j < nj) ? g_pooled_crop[j*OC + c] * (1.0f/256.0f) : 0.f;
        }
        __syncthreads();
        float acc[8] = {0.f,0.f,0.f,0.f,0.f,0.f,0.f,0.f};
        for (int c = 0; c < OC; c++) {
            float w = Wf[(long)c*FCO + o];
            #pragma unroll
            for (int jj = 0; jj < 8; jj++) acc[jj] += sp[jj*OC + c] * w;
        }
        float bias = bf[o];
        #pragma unroll
        for (int jj = 0; jj < 8; jj++) {
            int j = j0 + jj;
            if (j < nj)
                out[FEAT_OFF + (long)g_job_bk[j]*FCO + o] = acc[jj] + bias;
        }
    }
}

// ---------------------------------------------------------------- launch
extern "C" void kernel_launch(void* const* d_in, const int* in_sizes, int n_in,
                              void* d_out, int out_size) {
    const float* x      = (const float*)d_in[0];
    const float* boxes  = (const float*)d_in[1];
    const float* scores = (const float*)d_in[2];
    const void*  labels = d_in[3];
    const float* Wc     = (const float*)d_in[4];
    const float* bc     = (const float*)d_in[5];
    const float* Wf     = (const float*)d_in[6];
    const float* bf     = (const float*)d_in[7];
    float* out = (float*)d_out;

    cudaFuncSetAttribute(conv_kernel, cudaFuncAttributeMaxDynamicSharedMemorySize, CONV_SMEM);

    prep_kernel<<<320, 256>>>(Wc, (const long long*)labels);
    topk_kernel<<<BATCH, 32>>>(boxes, scores, labels, out);
    cudaMemsetAsync(out + FEAT_OFF, 0, (size_t)BATCH*TOPK*FCO*sizeof(float));
    sample_kernel<<<BATCH*TOPK, 256>>>(x);
    conv_kernel<<<FULL_BLOCKS + CROP_BLOCKS, 512, CONV_SMEM>>>(x, bc);
    fc_kernel<<<dim3(16, 21), 256>>>(Wf, bf, out);
}